// round 7
// baseline (speedup 1.0000x reference)
#include <cuda_runtime.h>
#include <math.h>
#include <stdint.h>

#define BB   4
#define CIN  128
#define COUT 128
#define HH   96
#define WW   96
#define K2   9

#define OUT_MAIN_ELEMS (BB*COUT*HH*WW)   // 4718592
#define PLANE (HH*WW)                    // 9216

// ---- device scratch (no allocations allowed) ----
__device__ float g_xt[BB*HH*WW*CIN];        // x in NHWC
__device__ float g_mask[BB*K2*PLANE];       // sigmoid(om[18:27])*2
__device__ float g_wt2[K2*4*128*32];        // tf32 main weights: [tap*4+cq][oc128][c32]
__device__ float g_wofft2[K2*4*32*32];      // tf32 offset weights: [tap*4+cq][oc32][c32]
__device__ float4 g_bw[BB*K2*PLANE];        // per (b,tap,px): 4 corner weights (mask folded)
__device__ int4   g_bi[BB*K2*PLANE];        // per (b,tap,px): 4 corner base idx (float4 units)

__device__ __forceinline__ uint32_t f2tf32(float x) {
    uint32_t u;
    asm("cvt.rna.tf32.f32 %0, %1;" : "=r"(u) : "f"(x));
    return u;
}
__device__ __forceinline__ uint32_t smem_u32(const void* p) {
    uint32_t a;
    asm("{ .reg .u64 t; cvta.to.shared.u64 t, %1; cvt.u32.u64 %0, t; }" : "=r"(a) : "l"(p));
    return a;
}
__device__ __forceinline__ void mma_tf32(float d[4], const uint32_t a[4], const uint32_t b[2]) {
    asm volatile(
        "mma.sync.aligned.m16n8k8.row.col.f32.tf32.tf32.f32 "
        "{%0,%1,%2,%3}, {%4,%5,%6,%7}, {%8,%9}, {%0,%1,%2,%3};"
        : "+f"(d[0]), "+f"(d[1]), "+f"(d[2]), "+f"(d[3])
        : "r"(a[0]), "r"(a[1]), "r"(a[2]), "r"(a[3]), "r"(b[0]), "r"(b[1]));
}
#define CP_ASYNC16(dst, src) \
    asm volatile("cp.async.cg.shared.global [%0], [%1], 16;" :: "r"(dst), "l"(src) : "memory")
#define CP_COMMIT() asm volatile("cp.async.commit_group;" ::: "memory")
#define CP_WAIT(n)  asm volatile("cp.async.wait_group %0;" :: "n"(n) : "memory")

// ============================================================
// 1) NCHW -> NHWC transpose of x
// ============================================================
__global__ void transpose_nchw_nhwc(const float* __restrict__ x) {
    __shared__ float t[32][33];
    int w0 = blockIdx.x * 32;
    int c0 = blockIdx.y * 32;
    int bh = blockIdx.z;
    int b = bh / HH;
    int h = bh % HH;
    const float* xb = x + (size_t)b * CIN * HH * WW;
#pragma unroll
    for (int i = 0; i < 32; i += 8) {
        int c = c0 + threadIdx.y + i;
        t[threadIdx.y + i][threadIdx.x] = xb[((size_t)c * HH + h) * WW + w0 + threadIdx.x];
    }
    __syncthreads();
    float* xt = g_xt + ((size_t)b * HH + h) * WW * CIN;
#pragma unroll
    for (int i = 0; i < 32; i += 8) {
        int w = w0 + threadIdx.y + i;
        xt[(size_t)w * CIN + c0 + threadIdx.x] = t[threadIdx.x][threadIdx.y + i];
    }
}

// ============================================================
// 2) Weight prep (tf32, chunked layouts)
// ============================================================
__global__ void transpose_weights(const float* __restrict__ weight,
                                  const float* __restrict__ w_off) {
    int idx = blockIdx.x * 256 + threadIdx.x;
    if (idx < K2 * CIN * COUT) {
        int tap = idx / (CIN * COUT);
        int r   = idx % (CIN * COUT);
        int c   = r >> 7;
        int oc  = r & 127;
        int blk = tap * 4 + (c >> 5);
        uint32_t tv = f2tf32(weight[((size_t)oc * CIN + c) * K2 + tap]);
        g_wt2[(size_t)blk * 4096 + oc * 32 + (c & 31)] = __uint_as_float(tv);
    }
    if (idx < K2 * 4 * 32 * 32) {
        int blk = idx >> 10;
        int e   = idx & 1023;
        int oc  = e >> 5;
        int c32 = e & 31;
        int tap = blk >> 2, cq = blk & 3;
        int c = cq * 32 + c32;
        float v = (oc < 27) ? w_off[((size_t)oc * CIN + c) * K2 + tap] : 0.f;
        g_wofft2[idx] = __uint_as_float(f2tf32(v));
    }
}

// ============================================================
// 3) Offset/mask conv via tf32 MMA (divides hoisted)
// ============================================================
__global__ __launch_bounds__(256)
void offset_mma(float* __restrict__ out_off) {
    __shared__ uint32_t As[256 * 36];
    __shared__ uint32_t Bs[32 * 36];

    int tid = threadIdx.x;
    int wid = tid >> 5, lane = tid & 31;
    int g = lane >> 2, t = lane & 3;
    int pix0 = blockIdx.x * 256;
    int wpx0 = wid * 32;

    int gp = tid >> 3;
    int gc = lane & 7;

    // hoist per-pass pixel decomposition out of the K loop
    int pp_b[8], pp_h[8], pp_w[8];
#pragma unroll
    for (int pass = 0; pass < 8; pass++) {
        int pixg = pix0 + pass * 32 + gp;
        pp_b[pass] = pixg / PLANE;
        int pr = pixg % PLANE;
        pp_h[pass] = pr / WW;
        pp_w[pass] = pr % WW;
    }

    float acc[2][4][4];
#pragma unroll
    for (int mt = 0; mt < 2; mt++)
#pragma unroll
        for (int nt = 0; nt < 4; nt++)
#pragma unroll
            for (int r = 0; r < 4; r++) acc[mt][nt][r] = 0.f;

    const float4* xt4 = (const float4*)g_xt;

    for (int chunk = 0; chunk < 36; ++chunk) {
        int tap = chunk >> 2, cq = chunk & 3;
        int ki = tap / 3, kj = tap % 3;
        __syncthreads();

        {
            const float4* bs = (const float4*)(g_wofft2 + (size_t)(tap * 4 + cq) * 1024);
            int oc = tid >> 3, c4 = (tid & 7) * 4;
            *(float4*)&Bs[oc * 36 + c4] = bs[tid];
        }

#pragma unroll
        for (int pass = 0; pass < 8; pass++) {
            int y = pp_h[pass] + ki - 1, x = pp_w[pass] + kj - 1;
            bool ok = (y >= 0) && (y < HH) && (x >= 0) && (x < WW);
            float4 v = make_float4(0.f, 0.f, 0.f, 0.f);
            if (ok) v = xt4[((size_t)pp_b[pass] * PLANE + y * WW + x) * 32 + cq * 8 + gc];
            uint32_t* dst = &As[(pass * 32 + gp) * 36 + gc * 4];
            dst[0] = f2tf32(v.x);
            dst[1] = f2tf32(v.y);
            dst[2] = f2tf32(v.z);
            dst[3] = f2tf32(v.w);
        }
        __syncthreads();

#pragma unroll
        for (int ks = 0; ks < 4; ks++) {
            int c0 = ks * 8 + t;
            uint32_t afrag[2][4];
#pragma unroll
            for (int mt = 0; mt < 2; mt++) {
                int row = wpx0 + mt * 16 + g;
                afrag[mt][0] = As[row * 36 + c0];
                afrag[mt][1] = As[(row + 8) * 36 + c0];
                afrag[mt][2] = As[row * 36 + c0 + 4];
                afrag[mt][3] = As[(row + 8) * 36 + c0 + 4];
            }
            uint32_t bfrag[4][2];
#pragma unroll
            for (int nt = 0; nt < 4; nt++) {
                int oc = nt * 8 + g;
                bfrag[nt][0] = Bs[oc * 36 + c0];
                bfrag[nt][1] = Bs[oc * 36 + c0 + 4];
            }
#pragma unroll
            for (int mt = 0; mt < 2; mt++)
#pragma unroll
                for (int nt = 0; nt < 4; nt++)
                    mma_tf32(acc[mt][nt], afrag[mt], bfrag[nt]);
        }
    }

#pragma unroll
    for (int nt = 0; nt < 4; nt++) {
        int oc0 = nt * 8 + 2 * t;
#pragma unroll
        for (int mt = 0; mt < 2; mt++) {
            int row = wpx0 + mt * 16 + g;
#pragma unroll
            for (int rr = 0; rr < 4; rr++) {
                int oc = oc0 + (rr & 1);
                int pixg = pix0 + row + (rr >> 1) * 8;
                float v = acc[mt][nt][rr];
                int b = pixg / PLANE;
                int pr = pixg % PLANE;
                if (oc < 18) {
                    out_off[((size_t)b * 18 + oc) * PLANE + pr] = v;
                } else if (oc < 27) {
                    g_mask[((size_t)b * 9 + (oc - 18)) * PLANE + pr] =
                        2.0f / (1.0f + expf(-v));
                }
            }
        }
    }
}

// ============================================================
// 4) Precompute bilinear params per (b, tap, px)
// ============================================================
__global__ void prep_bilinear(const float* __restrict__ off) {
    int idx = blockIdx.x * 256 + threadIdx.x;
    if (idx >= BB * K2 * PLANE) return;
    int b   = idx / (K2 * PLANE);
    int r   = idx % (K2 * PLANE);
    int tap = r / PLANE;
    int pix = r % PLANE;
    int h = pix / WW, w = pix % WW;

    float o1 = off[((size_t)b * 18 + tap) * PLANE + pix];
    float o2 = off[((size_t)b * 18 + 9 + tap) * PLANE + pix];
    float m  = g_mask[((size_t)b * 9 + tap) * PLANE + pix];

    int ki = tap / 3, kj = tap % 3;
    float py  = (float)(h - 1 + ki) + o1;
    float pxx = (float)(w - 1 + kj) + o2;
    float y0f = floorf(py), x0f = floorf(pxx);
    float ly = py - y0f, lx = pxx - x0f;
    float hy = 1.f - ly, hx = 1.f - lx;
    int y0 = (int)y0f, x0 = (int)x0f;
    int y1 = y0 + 1, x1 = x0 + 1;
    bool vy0 = (y0 >= 0) && (y0 < HH), vy1 = (y1 >= 0) && (y1 < HH);
    bool vx0 = (x0 >= 0) && (x0 < WW), vx1 = (x1 >= 0) && (x1 < WW);
    float4 wv;
    wv.x = (vy0 && vx0) ? hy * hx * m : 0.f;
    wv.y = (vy0 && vx1) ? hy * lx * m : 0.f;
    wv.z = (vy1 && vx0) ? ly * hx * m : 0.f;
    wv.w = (vy1 && vx1) ? ly * lx * m : 0.f;
    int y0c = min(max(y0, 0), HH - 1), y1c = min(max(y1, 0), HH - 1);
    int x0c = min(max(x0, 0), WW - 1), x1c = min(max(x1, 0), WW - 1);
    int4 iv;
    iv.x = (y0c * WW + x0c) * 32;
    iv.y = (y0c * WW + x1c) * 32;
    iv.z = (y1c * WW + x0c) * 32;
    iv.w = (y1c * WW + x1c) * 32;
    g_bw[idx] = wv;
    g_bi[idx] = iv;
}

// ============================================================
// 5) Deformable conv: per-tap cached indices, cp.async B pipeline
//    CTA: M=128 px x N=128 oc; K = 9 taps x 4 cq-chunks of 32 c.
//    dyn smem: As[128*36] + Bs[2][128*36] = 55296 B
// ============================================================
__global__ __launch_bounds__(256, 2)
void deform_mma(const float* __restrict__ bias,
                float* __restrict__ out) {
    extern __shared__ uint32_t dsm[];
    uint32_t* As = dsm;                 // 4608 words
    uint32_t* Bs = dsm + 4608;          // 2 x 4608 words
    uint32_t bs_base = smem_u32(Bs);

    int tid = threadIdx.x;
    int wid = tid >> 5, lane = tid & 31;
    int g = lane >> 2, t = lane & 3;
    int b   = blockIdx.z;
    int ho0 = blockIdx.y * 4;
    int wo0 = blockIdx.x * 32;

    int wpx0 = (wid & 3) * 32;
    int woc0 = (wid >> 2) * 64;

    int gp = tid >> 3;          // pixel slot within pass
    int gc = lane & 7;          // channel float4 slot

    float acc[2][8][4];
#pragma unroll
    for (int mt = 0; mt < 2; mt++)
#pragma unroll
        for (int nt = 0; nt < 8; nt++)
#pragma unroll
            for (int r = 0; r < 4; r++) acc[mt][nt][r] = 0.f;

    // per-pass pixel offsets within plane (constant across taps)
    int pixp[4];
#pragma unroll
    for (int pass = 0; pass < 4; pass++) {
        int p = pass * 32 + gp;
        pixp[pass] = (ho0 + (p >> 5)) * WW + wo0 + (p & 31);
    }

    const float4* xt4 = (const float4*)(g_xt + (size_t)b * PLANE * CIN);
    int pbase = (b * K2) * PLANE;

    // prologue: cp.async B chunk 0 into Bs buf 0
    {
        const float* wsrc = g_wt2;
#pragma unroll
        for (int j = 0; j < 4; j++) {
            int idx4 = tid + j * 256;
            int oc = idx4 >> 3, c4 = (idx4 & 7) * 4;
            CP_ASYNC16(bs_base + (oc * 36 + c4) * 4, wsrc + idx4 * 4);
        }
        CP_COMMIT();
    }

    for (int tap = 0; tap < 9; ++tap) {
        // per-tap corner indices (one indirection per tap, not per chunk)
        int4 iv4[4];
#pragma unroll
        for (int pass = 0; pass < 4; pass++)
            iv4[pass] = g_bi[pbase + tap * PLANE + pixp[pass]];

#pragma unroll 1
        for (int cq = 0; cq < 4; ++cq) {
            int chunk = tap * 4 + cq;
            __syncthreads();   // mma(chunk-1) finished reading As and Bs[(chunk+1)&1]

            // stream next chunk's weights (overlaps gather + mma below)
            if (chunk < 35) {
                const float* wsrc = g_wt2 + (size_t)(chunk + 1) * 4096;
                uint32_t dstb = bs_base + (((chunk + 1) & 1) * 4608) * 4;
#pragma unroll
                for (int j = 0; j < 4; j++) {
                    int idx4 = tid + j * 256;
                    int oc = idx4 >> 3, c4 = (idx4 & 7) * 4;
                    CP_ASYNC16(dstb + (oc * 36 + c4) * 4, wsrc + idx4 * 4);
                }
                CP_COMMIT();
            }

            // gather + modulate 32 channels -> As (no dependent-chain loads)
#pragma unroll
            for (int pass = 0; pass < 4; pass++) {
                float4 wv = g_bw[pbase + tap * PLANE + pixp[pass]];
                int4 iv = iv4[pass];
                int cc = cq * 8 + gc;
                float4 v00 = xt4[iv.x + cc];
                float4 v01 = xt4[iv.y + cc];
                float4 v10 = xt4[iv.z + cc];
                float4 v11 = xt4[iv.w + cc];
                uint32_t* dst = &As[(pass * 32 + gp) * 36 + gc * 4];
                dst[0] = f2tf32(wv.x * v00.x + wv.y * v01.x + wv.z * v10.x + wv.w * v11.x);
                dst[1] = f2tf32(wv.x * v00.y + wv.y * v01.y + wv.z * v10.y + wv.w * v11.y);
                dst[2] = f2tf32(wv.x * v00.z + wv.y * v01.z + wv.z * v10.z + wv.w * v11.z);
                dst[3] = f2tf32(wv.x * v00.w + wv.y * v01.w + wv.z * v10.w + wv.w * v11.w);
            }

            if (chunk < 35) { CP_WAIT(1); } else { CP_WAIT(0); }
            __syncthreads();

            // mma from As, Bs[chunk&1]
            const uint32_t* bsc = Bs + (chunk & 1) * 4608;
#pragma unroll
            for (int ks = 0; ks < 4; ks++) {
                int c0 = ks * 8 + t;
                uint32_t afrag[2][4];
#pragma unroll
                for (int mt = 0; mt < 2; mt++) {
                    int row = wpx0 + mt * 16 + g;
                    afrag[mt][0] = As[row * 36 + c0];
                    afrag[mt][1] = As[(row + 8) * 36 + c0];
                    afrag[mt][2] = As[row * 36 + c0 + 4];
                    afrag[mt][3] = As[(row + 8) * 36 + c0 + 4];
                }
                uint32_t bfrag[8][2];
#pragma unroll
                for (int nt = 0; nt < 8; nt++) {
                    int oc = woc0 + nt * 8 + g;
                    bfrag[nt][0] = bsc[oc * 36 + c0];
                    bfrag[nt][1] = bsc[oc * 36 + c0 + 4];
                }
#pragma unroll
                for (int mt = 0; mt < 2; mt++)
#pragma unroll
                    for (int nt = 0; nt < 8; nt++)
                        mma_tf32(acc[mt][nt], afrag[mt], bfrag[nt]);
            }
        }
    }

    // epilogue: acc -> out (NCHW) + bias
    int e_ho = ho0 + (wid & 3);
    float* ob = out + ((size_t)b * COUT) * PLANE + (size_t)e_ho * WW + wo0;
#pragma unroll
    for (int nt = 0; nt < 8; nt++) {
        int oc0 = woc0 + nt * 8 + 2 * t;
        float b0 = __ldg(&bias[oc0]);
        float b1 = __ldg(&bias[oc0 + 1]);
#pragma unroll
        for (int mt = 0; mt < 2; mt++) {
            int wo_a = mt * 16 + g;
            float* r0 = ob + (size_t)oc0 * PLANE + wo_a;
            float* r1 = ob + (size_t)(oc0 + 1) * PLANE + wo_a;
            r0[0] = acc[mt][nt][0] + b0;
            r1[0] = acc[mt][nt][1] + b1;
            r0[8] = acc[mt][nt][2] + b0;
            r1[8] = acc[mt][nt][3] + b1;
        }
    }
}

// ============================================================
// launch
// ============================================================
extern "C" void kernel_launch(void* const* d_in, const int* in_sizes, int n_in,
                              void* d_out, int out_size) {
    (void)in_sizes; (void)n_in; (void)out_size;
    const float* x      = (const float*)d_in[0];
    const float* weight = (const float*)d_in[1];
    const float* bias   = (const float*)d_in[2];
    const float* w_off  = (const float*)d_in[3];

    float* out = (float*)d_out;
    float* off = out + OUT_MAIN_ELEMS;   // second output: offsets [B,18,H,W]

    const int DSMEM = (4608 + 2 * 4608) * 4;   // 55296 B
    cudaFuncSetAttribute(deform_mma, cudaFuncAttributeMaxDynamicSharedMemorySize, DSMEM);

    transpose_nchw_nhwc<<<dim3(WW / 32, CIN / 32, BB * HH), dim3(32, 8)>>>(x);
    transpose_weights<<<(K2 * CIN * COUT + 255) / 256, 256>>>(weight, w_off);
    offset_mma<<<(BB * PLANE) / 256, 256>>>(off);
    prep_bilinear<<<(BB * K2 * PLANE + 255) / 256, 256>>>(off);
    deform_mma<<<dim3(WW / 32, HH / 4, BB), 256, DSMEM>>>(bias, out);
}

// round 8
// speedup vs baseline: 1.3064x; 1.3064x over previous
#include <cuda_runtime.h>
#include <cuda_fp16.h>
#include <math.h>
#include <stdint.h>

#define BB   4
#define CIN  128
#define COUT 128
#define HH   96
#define WW   96
#define K2   9

#define OUT_MAIN_ELEMS (BB*COUT*HH*WW)   // 4718592
#define PLANE (HH*WW)                    // 9216

// ---- device scratch (no allocations allowed) ----
__device__ float    g_xt[BB*HH*WW*CIN];      // x in NHWC
__device__ float    g_mask[BB*K2*PLANE];     // sigmoid(om[18:27])*2
__device__ uint32_t g_wt16[36*128*16];       // fp16x2 main weights: [chunk][oc128][cpair16]
__device__ uint32_t g_wofft16[36*32*16];     // fp16x2 offset weights: [chunk][oc32][cpair16]
__device__ float4   g_bw[BB*K2*PLANE];       // per (b,tap,px): 4 corner weights (mask folded)
__device__ int4     g_bi[BB*K2*PLANE];       // per (b,tap,px): 4 corner base idx (float4 units)

__device__ __forceinline__ uint32_t pack_h2(float lo, float hi) {
    __half2 h = __floats2half2_rn(lo, hi);
    return *(uint32_t*)&h;
}
__device__ __forceinline__ uint32_t smem_u32(const void* p) {
    uint32_t a;
    asm("{ .reg .u64 t; cvta.to.shared.u64 t, %1; cvt.u32.u64 %0, t; }" : "=r"(a) : "l"(p));
    return a;
}
__device__ __forceinline__ void mma_f16(float d[4], const uint32_t a[4], const uint32_t b[2]) {
    asm volatile(
        "mma.sync.aligned.m16n8k16.row.col.f32.f16.f16.f32 "
        "{%0,%1,%2,%3}, {%4,%5,%6,%7}, {%8,%9}, {%0,%1,%2,%3};"
        : "+f"(d[0]), "+f"(d[1]), "+f"(d[2]), "+f"(d[3])
        : "r"(a[0]), "r"(a[1]), "r"(a[2]), "r"(a[3]), "r"(b[0]), "r"(b[1]));
}
#define CP_ASYNC16(dst, src) \
    asm volatile("cp.async.cg.shared.global [%0], [%1], 16;" :: "r"(dst), "l"(src) : "memory")
#define CP_COMMIT() asm volatile("cp.async.commit_group;" ::: "memory")
#define CP_WAIT(n)  asm volatile("cp.async.wait_group %0;" :: "n"(n) : "memory")

#define SA 20   // smem row stride in words (conflict-free: g*20 mod 32 4-spaced)

// ============================================================
// 1) NCHW -> NHWC transpose of x
// ============================================================
__global__ void transpose_nchw_nhwc(const float* __restrict__ x) {
    __shared__ float t[32][33];
    int w0 = blockIdx.x * 32;
    int c0 = blockIdx.y * 32;
    int bh = blockIdx.z;
    int b = bh / HH;
    int h = bh % HH;
    const float* xb = x + (size_t)b * CIN * HH * WW;
#pragma unroll
    for (int i = 0; i < 32; i += 8) {
        int c = c0 + threadIdx.y + i;
        t[threadIdx.y + i][threadIdx.x] = xb[((size_t)c * HH + h) * WW + w0 + threadIdx.x];
    }
    __syncthreads();
    float* xt = g_xt + ((size_t)b * HH + h) * WW * CIN;
#pragma unroll
    for (int i = 0; i < 32; i += 8) {
        int w = w0 + threadIdx.y + i;
        xt[(size_t)w * CIN + c0 + threadIdx.x] = t[threadIdx.x][threadIdx.y + i];
    }
}

// ============================================================
// 2) Weight prep -> fp16x2 pair layouts
// ============================================================
__global__ void prep_weights(const float* __restrict__ weight,
                             const float* __restrict__ w_off) {
    int idx = blockIdx.x * 256 + threadIdx.x;
    if (idx < 36 * 128 * 16) {          // main: pair idx
        int chunk = idx >> 11;          // /2048
        int r     = idx & 2047;
        int oc    = r >> 4;
        int j     = r & 15;
        int tap   = chunk >> 2;
        int c     = (chunk & 3) * 32 + 2 * j;
        float w0 = weight[((size_t)oc * CIN + c) * K2 + tap];
        float w1 = weight[((size_t)oc * CIN + c + 1) * K2 + tap];
        g_wt16[idx] = pack_h2(w0, w1);
    }
    if (idx < 36 * 32 * 16) {           // offset weights (27 padded to 32)
        int chunk = idx >> 9;           // /512
        int r     = idx & 511;
        int oc    = r >> 4;
        int j     = r & 15;
        int tap   = chunk >> 2;
        int c     = (chunk & 3) * 32 + 2 * j;
        float w0 = 0.f, w1 = 0.f;
        if (oc < 27) {
            w0 = w_off[((size_t)oc * CIN + c) * K2 + tap];
            w1 = w_off[((size_t)oc * CIN + c + 1) * K2 + tap];
        }
        g_wofft16[idx] = pack_h2(w0, w1);
    }
}

// ============================================================
// 3) Offset/mask conv via fp16 MMA.
//    CTA: 256 px x 32 oc; K = 36 chunks of 32 c (2 k16 steps each).
// ============================================================
__global__ __launch_bounds__(256)
void offset_mma(float* __restrict__ out_off) {
    __shared__ uint32_t As[256 * SA];   // 20KB
    __shared__ uint32_t Bs[32 * SA];    // 2.5KB

    int tid = threadIdx.x;
    int wid = tid >> 5, lane = tid & 31;
    int g = lane >> 2, t = lane & 3;
    int pix0 = blockIdx.x * 256;
    int wpx0 = wid * 32;

    int gp = tid >> 3;
    int gc = lane & 7;

    int pp_b[8], pp_h[8], pp_w[8];
#pragma unroll
    for (int pass = 0; pass < 8; pass++) {
        int pixg = pix0 + pass * 32 + gp;
        pp_b[pass] = pixg / PLANE;
        int pr = pixg % PLANE;
        pp_h[pass] = pr / WW;
        pp_w[pass] = pr % WW;
    }

    float acc[2][4][4];
#pragma unroll
    for (int mt = 0; mt < 2; mt++)
#pragma unroll
        for (int nt = 0; nt < 4; nt++)
#pragma unroll
            for (int r = 0; r < 4; r++) acc[mt][nt][r] = 0.f;

    const float4* xt4 = (const float4*)g_xt;

    for (int chunk = 0; chunk < 36; ++chunk) {
        int tap = chunk >> 2, cq = chunk & 3;
        int ki = tap / 3, kj = tap % 3;
        __syncthreads();

        // stage Bs [32oc][16 pairs], 2 words/thread
        {
            const uint32_t* bs = g_wofft16 + (size_t)chunk * 512;
            int oc = tid >> 3, jw = (tid & 7) * 2;
            *(uint2*)&Bs[oc * SA + jw] = *(const uint2*)&bs[oc * 16 + jw];
        }

#pragma unroll
        for (int pass = 0; pass < 8; pass++) {
            int y = pp_h[pass] + ki - 1, x = pp_w[pass] + kj - 1;
            bool ok = (y >= 0) && (y < HH) && (x >= 0) && (x < WW);
            float4 v = make_float4(0.f, 0.f, 0.f, 0.f);
            if (ok) v = xt4[((size_t)pp_b[pass] * PLANE + y * WW + x) * 32 + cq * 8 + gc];
            uint2 pk = make_uint2(pack_h2(v.x, v.y), pack_h2(v.z, v.w));
            *(uint2*)&As[(pass * 32 + gp) * SA + gc * 2] = pk;
        }
        __syncthreads();

#pragma unroll
        for (int ks = 0; ks < 2; ks++) {
            int c0 = ks * 8 + t;
            uint32_t afrag[2][4];
#pragma unroll
            for (int mt = 0; mt < 2; mt++) {
                int row = wpx0 + mt * 16 + g;
                afrag[mt][0] = As[row * SA + c0];
                afrag[mt][1] = As[(row + 8) * SA + c0];
                afrag[mt][2] = As[row * SA + c0 + 4];
                afrag[mt][3] = As[(row + 8) * SA + c0 + 4];
            }
            uint32_t bfrag[4][2];
#pragma unroll
            for (int nt = 0; nt < 4; nt++) {
                int oc = nt * 8 + g;
                bfrag[nt][0] = Bs[oc * SA + c0];
                bfrag[nt][1] = Bs[oc * SA + c0 + 4];
            }
#pragma unroll
            for (int mt = 0; mt < 2; mt++)
#pragma unroll
                for (int nt = 0; nt < 4; nt++)
                    mma_f16(acc[mt][nt], afrag[mt], bfrag[nt]);
        }
    }

#pragma unroll
    for (int nt = 0; nt < 4; nt++) {
        int oc0 = nt * 8 + 2 * t;
#pragma unroll
        for (int mt = 0; mt < 2; mt++) {
            int row = wpx0 + mt * 16 + g;
#pragma unroll
            for (int rr = 0; rr < 4; rr++) {
                int oc = oc0 + (rr & 1);
                int pixg = pix0 + row + (rr >> 1) * 8;
                float v = acc[mt][nt][rr];
                int b = pixg / PLANE;
                int pr = pixg % PLANE;
                if (oc < 18) {
                    out_off[((size_t)b * 18 + oc) * PLANE + pr] = v;
                } else if (oc < 27) {
                    g_mask[((size_t)b * 9 + (oc - 18)) * PLANE + pr] =
                        2.0f / (1.0f + expf(-v));
                }
            }
        }
    }
}

// ============================================================
// 4) Precompute bilinear params per (b, tap, px)
// ============================================================
__global__ void prep_bilinear(const float* __restrict__ off) {
    int idx = blockIdx.x * 256 + threadIdx.x;
    if (idx >= BB * K2 * PLANE) return;
    int b   = idx / (K2 * PLANE);
    int r   = idx % (K2 * PLANE);
    int tap = r / PLANE;
    int pix = r % PLANE;
    int h = pix / WW, w = pix % WW;

    float o1 = off[((size_t)b * 18 + tap) * PLANE + pix];
    float o2 = off[((size_t)b * 18 + 9 + tap) * PLANE + pix];
    float m  = g_mask[((size_t)b * 9 + tap) * PLANE + pix];

    int ki = tap / 3, kj = tap % 3;
    float py  = (float)(h - 1 + ki) + o1;
    float pxx = (float)(w - 1 + kj) + o2;
    float y0f = floorf(py), x0f = floorf(pxx);
    float ly = py - y0f, lx = pxx - x0f;
    float hy = 1.f - ly, hx = 1.f - lx;
    int y0 = (int)y0f, x0 = (int)x0f;
    int y1 = y0 + 1, x1 = x0 + 1;
    bool vy0 = (y0 >= 0) && (y0 < HH), vy1 = (y1 >= 0) && (y1 < HH);
    bool vx0 = (x0 >= 0) && (x0 < WW), vx1 = (x1 >= 0) && (x1 < WW);
    float4 wv;
    wv.x = (vy0 && vx0) ? hy * hx * m : 0.f;
    wv.y = (vy0 && vx1) ? hy * lx * m : 0.f;
    wv.z = (vy1 && vx0) ? ly * hx * m : 0.f;
    wv.w = (vy1 && vx1) ? ly * lx * m : 0.f;
    int y0c = min(max(y0, 0), HH - 1), y1c = min(max(y1, 0), HH - 1);
    int x0c = min(max(x0, 0), WW - 1), x1c = min(max(x1, 0), WW - 1);
    int4 iv;
    iv.x = (y0c * WW + x0c) * 32;
    iv.y = (y0c * WW + x1c) * 32;
    iv.z = (y1c * WW + x0c) * 32;
    iv.w = (y1c * WW + x1c) * 32;
    g_bw[idx] = wv;
    g_bi[idx] = iv;
}

// ============================================================
// 5) Deformable conv: gather -> fp16 smem -> m16n8k16 MMA
//    CTA: M=128 px x N=128 oc; 36 chunks of 32 c.
//    dyn smem: As[128*SA] + Bs[2][128*SA] = 30720 B
// ============================================================
__global__ __launch_bounds__(256, 2)
void deform_mma(const float* __restrict__ bias,
                float* __restrict__ out) {
    extern __shared__ uint32_t dsm[];
    uint32_t* As = dsm;                    // 2560 words
    uint32_t* Bs = dsm + 128 * SA;         // 2 x 2560 words
    uint32_t bs_base = smem_u32(Bs);

    int tid = threadIdx.x;
    int wid = tid >> 5, lane = tid & 31;
    int g = lane >> 2, t = lane & 3;
    int b   = blockIdx.z;
    int ho0 = blockIdx.y * 4;
    int wo0 = blockIdx.x * 32;

    int wpx0 = (wid & 3) * 32;
    int woc0 = (wid >> 2) * 64;

    int gp = tid >> 3;
    int gc = lane & 7;

    float acc[2][8][4];
#pragma unroll
    for (int mt = 0; mt < 2; mt++)
#pragma unroll
        for (int nt = 0; nt < 8; nt++)
#pragma unroll
            for (int r = 0; r < 4; r++) acc[mt][nt][r] = 0.f;

    int pixp[4];
#pragma unroll
    for (int pass = 0; pass < 4; pass++) {
        int p = pass * 32 + gp;
        pixp[pass] = (ho0 + (p >> 5)) * WW + wo0 + (p & 31);
    }

    const float4* xt4 = (const float4*)(g_xt + (size_t)b * PLANE * CIN);
    int pbase = (b * K2) * PLANE;

    // prologue: cp.async B chunk 0 (128 oc x 16 words = 8KB), 2 x 16B per thread
    {
        const uint32_t* wsrc = g_wt16;
#pragma unroll
        for (int k = 0; k < 2; k++) {
            int idx = tid + k * 256;
            int oc = idx >> 2, j = (idx & 3) * 4;
            CP_ASYNC16(bs_base + (oc * SA + j) * 4, wsrc + oc * 16 + j);
        }
        CP_COMMIT();
    }

    for (int tap = 0; tap < 9; ++tap) {
        int4 iv4[4];
        float4 wv4[4];
#pragma unroll
        for (int pass = 0; pass < 4; pass++) {
            iv4[pass] = g_bi[pbase + tap * PLANE + pixp[pass]];
            wv4[pass] = g_bw[pbase + tap * PLANE + pixp[pass]];
        }

#pragma unroll 1
        for (int cq = 0; cq < 4; ++cq) {
            int chunk = tap * 4 + cq;
            __syncthreads();

            if (chunk < 35) {
                const uint32_t* wsrc = g_wt16 + (size_t)(chunk + 1) * 2048;
                uint32_t dstb = bs_base + (((chunk + 1) & 1) * 128 * SA) * 4;
#pragma unroll
                for (int k = 0; k < 2; k++) {
                    int idx = tid + k * 256;
                    int oc = idx >> 2, j = (idx & 3) * 4;
                    CP_ASYNC16(dstb + (oc * SA + j) * 4, wsrc + oc * 16 + j);
                }
                CP_COMMIT();
            }

            // gather + modulate -> fp16 pairs in As
#pragma unroll
            for (int pass = 0; pass < 4; pass++) {
                float4 wv = wv4[pass];
                int4 iv = iv4[pass];
                int cc = cq * 8 + gc;
                float4 v00 = xt4[iv.x + cc];
                float4 v01 = xt4[iv.y + cc];
                float4 v10 = xt4[iv.z + cc];
                float4 v11 = xt4[iv.w + cc];
                float r0 = wv.x * v00.x + wv.y * v01.x + wv.z * v10.x + wv.w * v11.x;
                float r1 = wv.x * v00.y + wv.y * v01.y + wv.z * v10.y + wv.w * v11.y;
                float r2 = wv.x * v00.z + wv.y * v01.z + wv.z * v10.z + wv.w * v11.z;
                float r3 = wv.x * v00.w + wv.y * v01.w + wv.z * v10.w + wv.w * v11.w;
                uint2 pk = make_uint2(pack_h2(r0, r1), pack_h2(r2, r3));
                *(uint2*)&As[(pass * 32 + gp) * SA + gc * 2] = pk;
            }

            if (chunk < 35) { CP_WAIT(1); } else { CP_WAIT(0); }
            __syncthreads();

            const uint32_t* bsc = Bs + (chunk & 1) * 128 * SA;
#pragma unroll
            for (int ks = 0; ks < 2; ks++) {
                int c0 = ks * 8 + t;
                uint32_t afrag[2][4];
#pragma unroll
                for (int mt = 0; mt < 2; mt++) {
                    int row = wpx0 + mt * 16 + g;
                    afrag[mt][0] = As[row * SA + c0];
                    afrag[mt][1] = As[(row + 8) * SA + c0];
                    afrag[mt][2] = As[row * SA + c0 + 4];
                    afrag[mt][3] = As[(row + 8) * SA + c0 + 4];
                }
                uint32_t bfrag[8][2];
#pragma unroll
                for (int nt = 0; nt < 8; nt++) {
                    int oc = woc0 + nt * 8 + g;
                    bfrag[nt][0] = bsc[oc * SA + c0];
                    bfrag[nt][1] = bsc[oc * SA + c0 + 4];
                }
#pragma unroll
                for (int mt = 0; mt < 2; mt++)
#pragma unroll
                    for (int nt = 0; nt < 8; nt++)
                        mma_f16(acc[mt][nt], afrag[mt], bfrag[nt]);
            }
        }
    }

    // epilogue: acc -> out (NCHW) + bias
    int e_ho = ho0 + (wid & 3);
    float* ob = out + ((size_t)b * COUT) * PLANE + (size_t)e_ho * WW + wo0;
#pragma unroll
    for (int nt = 0; nt < 8; nt++) {
        int oc0 = woc0 + nt * 8 + 2 * t;
        float b0 = __ldg(&bias[oc0]);
        float b1 = __ldg(&bias[oc0 + 1]);
#pragma unroll
        for (int mt = 0; mt < 2; mt++) {
            int wo_a = mt * 16 + g;
            float* r0 = ob + (size_t)oc0 * PLANE + wo_a;
            float* r1 = ob + (size_t)(oc0 + 1) * PLANE + wo_a;
            r0[0] = acc[mt][nt][0] + b0;
            r1[0] = acc[mt][nt][1] + b1;
            r0[8] = acc[mt][nt][2] + b0;
            r1[8] = acc[mt][nt][3] + b1;
        }
    }
}

// ============================================================
// launch
// ============================================================
extern "C" void kernel_launch(void* const* d_in, const int* in_sizes, int n_in,
                              void* d_out, int out_size) {
    (void)in_sizes; (void)n_in; (void)out_size;
    const float* x      = (const float*)d_in[0];
    const float* weight = (const float*)d_in[1];
    const float* bias   = (const float*)d_in[2];
    const float* w_off  = (const float*)d_in[3];

    float* out = (float*)d_out;
    float* off = out + OUT_MAIN_ELEMS;   // second output: offsets [B,18,H,W]

    const int DSMEM = (128 * SA * 3) * 4;   // 30720 B
    cudaFuncSetAttribute(deform_mma, cudaFuncAttributeMaxDynamicSharedMemorySize, DSMEM);

    transpose_nchw_nhwc<<<dim3(WW / 32, CIN / 32, BB * HH), dim3(32, 8)>>>(x);
    prep_weights<<<(36 * 128 * 16 + 255) / 256, 256>>>(weight, w_off);
    offset_mma<<<(BB * PLANE) / 256, 256>>>(off);
    prep_bilinear<<<(BB * K2 * PLANE + 255) / 256, 256>>>(off);
    deform_mma<<<dim3(WW / 32, HH / 4, BB), 256, DSMEM>>>(bias, out);
}

// round 9
// speedup vs baseline: 1.9909x; 1.5239x over previous
#include <cuda_runtime.h>
#include <cuda_fp16.h>
#include <math.h>
#include <stdint.h>

#define BB   4
#define CIN  128
#define COUT 128
#define HH   96
#define WW   96
#define K2   9

#define OUT_MAIN_ELEMS (BB*COUT*HH*WW)   // 4718592
#define PLANE (HH*WW)                    // 9216

#define SA 36   // smem row stride (words) for 64-c fp16 tiles: 32 data + 4 pad

// ---- device scratch (no allocations allowed) ----
__device__ uint4    g_xh[BB*PLANE*16];       // x in NHWC fp16: 16 uint4 (=128 halves) per px
__device__ float    g_mask[BB*K2*PLANE];     // sigmoid(om[18:27])*2
__device__ uint32_t g_wt16[18*128*32];       // fp16x2 main weights: [chunk64][oc128][cpair32]
__device__ uint32_t g_wofft16[18*32*32];     // fp16x2 offset weights: [chunk64][oc32][cpair32]
__device__ float4   g_bw[BB*K2*PLANE];       // per (b,tap,px): 4 corner weights (mask folded)
__device__ int4     g_bi[BB*K2*PLANE];       // per (b,tap,px): 4 corner base idx (uint4 units)

__device__ __forceinline__ uint32_t pack_h2(float lo, float hi) {
    __half2 h = __floats2half2_rn(lo, hi);
    return *(uint32_t*)&h;
}
__device__ __forceinline__ uint32_t smem_u32(const void* p) {
    uint32_t a;
    asm("{ .reg .u64 t; cvta.to.shared.u64 t, %1; cvt.u32.u64 %0, t; }" : "=r"(a) : "l"(p));
    return a;
}
__device__ __forceinline__ void mma_f16(float d[4], const uint32_t a[4], const uint32_t b[2]) {
    asm volatile(
        "mma.sync.aligned.m16n8k16.row.col.f32.f16.f16.f32 "
        "{%0,%1,%2,%3}, {%4,%5,%6,%7}, {%8,%9}, {%0,%1,%2,%3};"
        : "+f"(d[0]), "+f"(d[1]), "+f"(d[2]), "+f"(d[3])
        : "r"(a[0]), "r"(a[1]), "r"(a[2]), "r"(a[3]), "r"(b[0]), "r"(b[1]));
}
#define CP_ASYNC16(dst, src) \
    asm volatile("cp.async.cg.shared.global [%0], [%1], 16;" :: "r"(dst), "l"(src) : "memory")
#define CP_COMMIT() asm volatile("cp.async.commit_group;" ::: "memory")
#define CP_WAIT(n)  asm volatile("cp.async.wait_group %0;" :: "n"(n) : "memory")

// ============================================================
// 1) NCHW fp32 -> NHWC fp16
// ============================================================
__global__ void transpose_to_fp16(const float* __restrict__ x) {
    __shared__ float t[32][33];
    int w0 = blockIdx.x * 32;
    int c0 = blockIdx.y * 32;
    int bh = blockIdx.z;
    int b = bh / HH;
    int h = bh % HH;
    const float* xb = x + (size_t)b * CIN * HH * WW;
#pragma unroll
    for (int i = 0; i < 32; i += 8) {
        int c = c0 + threadIdx.y + i;
        t[threadIdx.y + i][threadIdx.x] = xb[((size_t)c * HH + h) * WW + w0 + threadIdx.x];
    }
    __syncthreads();
    __half* xh = (__half*)g_xh + ((size_t)b * PLANE + h * WW) * CIN;
#pragma unroll
    for (int i = 0; i < 32; i += 8) {
        int w = w0 + threadIdx.y + i;
        xh[(size_t)w * CIN + c0 + threadIdx.x] = __float2half_rn(t[threadIdx.x][threadIdx.y + i]);
    }
}

// ============================================================
// 2) Weight prep -> fp16x2, 64-channel chunk layouts
// ============================================================
__global__ void prep_weights(const float* __restrict__ weight,
                             const float* __restrict__ w_off) {
    int idx = blockIdx.x * 256 + threadIdx.x;
    if (idx < 18 * 128 * 32) {          // main
        int chunk = idx >> 12;          // /4096
        int r     = idx & 4095;
        int oc    = r >> 5;
        int j     = r & 31;
        int c     = (chunk & 1) * 64 + 2 * j;
        int tap   = chunk >> 1;
        float w0 = weight[((size_t)oc * CIN + c) * K2 + tap];
        float w1 = weight[((size_t)oc * CIN + c + 1) * K2 + tap];
        g_wt16[idx] = pack_h2(w0, w1);
    }
    if (idx < 18 * 32 * 32) {           // offset (27 padded to 32)
        int chunk = idx >> 10;
        int r     = idx & 1023;
        int oc    = r >> 5;
        int j     = r & 31;
        int c     = (chunk & 1) * 64 + 2 * j;
        int tap   = chunk >> 1;
        float w0 = 0.f, w1 = 0.f;
        if (oc < 27) {
            w0 = w_off[((size_t)oc * CIN + c) * K2 + tap];
            w1 = w_off[((size_t)oc * CIN + c + 1) * K2 + tap];
        }
        g_wofft16[idx] = pack_h2(w0, w1);
    }
}

// ============================================================
// 3) Offset/mask conv via fp16 MMA (x already fp16 -> zero-convert A path)
//    CTA: 256 px x 32 oc; 18 chunks of 64 c (4 k16 steps each).
// ============================================================
__global__ __launch_bounds__(256)
void offset_mma(float* __restrict__ out_off) {
    __shared__ uint32_t As[256 * SA];   // 36KB
    __shared__ uint32_t Bs[32 * SA];    // 4.5KB

    int tid = threadIdx.x;
    int wid = tid >> 5, lane = tid & 31;
    int g = lane >> 2, t = lane & 3;
    int pix0 = blockIdx.x * 256;
    int wpx0 = wid * 32;

    int gp = tid >> 3;
    int gc = lane & 7;

    int pp_b[8], pp_h[8], pp_w[8];
#pragma unroll
    for (int pass = 0; pass < 8; pass++) {
        int pixg = pix0 + pass * 32 + gp;
        pp_b[pass] = pixg / PLANE;
        int pr = pixg % PLANE;
        pp_h[pass] = pr / WW;
        pp_w[pass] = pr % WW;
    }

    float acc[2][4][4];
#pragma unroll
    for (int mt = 0; mt < 2; mt++)
#pragma unroll
        for (int nt = 0; nt < 4; nt++)
#pragma unroll
            for (int r = 0; r < 4; r++) acc[mt][nt][r] = 0.f;

    for (int chunk = 0; chunk < 18; ++chunk) {
        int tap = chunk >> 1, cq = chunk & 1;
        int ki = tap / 3, kj = tap % 3;
        __syncthreads();

        // stage Bs [32oc][32 pairs], 4 words/thread
        {
            const uint32_t* bs = g_wofft16 + (size_t)chunk * 1024;
            int oc = tid >> 3, jw = (tid & 7) * 4;
            *(uint4*)&Bs[oc * SA + jw] = *(const uint4*)&bs[oc * 32 + jw];
        }

#pragma unroll
        for (int pass = 0; pass < 8; pass++) {
            int y = pp_h[pass] + ki - 1, x = pp_w[pass] + kj - 1;
            bool ok = (y >= 0) && (y < HH) && (x >= 0) && (x < WW);
            uint4 v = make_uint4(0u, 0u, 0u, 0u);
            if (ok) v = g_xh[((size_t)pp_b[pass] * PLANE + y * WW + x) * 16 + cq * 8 + gc];
            *(uint4*)&As[(pass * 32 + gp) * SA + gc * 4] = v;
        }
        __syncthreads();

#pragma unroll
        for (int ks = 0; ks < 4; ks++) {
            int c0 = ks * 8 + t;
            uint32_t afrag[2][4];
#pragma unroll
            for (int mt = 0; mt < 2; mt++) {
                int row = wpx0 + mt * 16 + g;
                afrag[mt][0] = As[row * SA + c0];
                afrag[mt][1] = As[(row + 8) * SA + c0];
                afrag[mt][2] = As[row * SA + c0 + 4];
                afrag[mt][3] = As[(row + 8) * SA + c0 + 4];
            }
            uint32_t bfrag[4][2];
#pragma unroll
            for (int nt = 0; nt < 4; nt++) {
                int oc = nt * 8 + g;
                bfrag[nt][0] = Bs[oc * SA + c0];
                bfrag[nt][1] = Bs[oc * SA + c0 + 4];
            }
#pragma unroll
            for (int mt = 0; mt < 2; mt++)
#pragma unroll
                for (int nt = 0; nt < 4; nt++)
                    mma_f16(acc[mt][nt], afrag[mt], bfrag[nt]);
        }
    }

#pragma unroll
    for (int nt = 0; nt < 4; nt++) {
        int oc0 = nt * 8 + 2 * t;
#pragma unroll
        for (int mt = 0; mt < 2; mt++) {
            int row = wpx0 + mt * 16 + g;
#pragma unroll
            for (int rr = 0; rr < 4; rr++) {
                int oc = oc0 + (rr & 1);
                int pixg = pix0 + row + (rr >> 1) * 8;
                float v = acc[mt][nt][rr];
                int b = pixg / PLANE;
                int pr = pixg % PLANE;
                if (oc < 18) {
                    out_off[((size_t)b * 18 + oc) * PLANE + pr] = v;
                } else if (oc < 27) {
                    g_mask[((size_t)b * 9 + (oc - 18)) * PLANE + pr] =
                        2.0f / (1.0f + expf(-v));
                }
            }
        }
    }
}

// ============================================================
// 4) Precompute bilinear params per (b, tap, px)
// ============================================================
__global__ void prep_bilinear(const float* __restrict__ off) {
    int idx = blockIdx.x * 256 + threadIdx.x;
    if (idx >= BB * K2 * PLANE) return;
    int b   = idx / (K2 * PLANE);
    int r   = idx % (K2 * PLANE);
    int tap = r / PLANE;
    int pix = r % PLANE;
    int h = pix / WW, w = pix % WW;

    float o1 = off[((size_t)b * 18 + tap) * PLANE + pix];
    float o2 = off[((size_t)b * 18 + 9 + tap) * PLANE + pix];
    float m  = g_mask[((size_t)b * 9 + tap) * PLANE + pix];

    int ki = tap / 3, kj = tap % 3;
    float py  = (float)(h - 1 + ki) + o1;
    float pxx = (float)(w - 1 + kj) + o2;
    float y0f = floorf(py), x0f = floorf(pxx);
    float ly = py - y0f, lx = pxx - x0f;
    float hy = 1.f - ly, hx = 1.f - lx;
    int y0 = (int)y0f, x0 = (int)x0f;
    int y1 = y0 + 1, x1 = x0 + 1;
    bool vy0 = (y0 >= 0) && (y0 < HH), vy1 = (y1 >= 0) && (y1 < HH);
    bool vx0 = (x0 >= 0) && (x0 < WW), vx1 = (x1 >= 0) && (x1 < WW);
    float4 wv;
    wv.x = (vy0 && vx0) ? hy * hx * m : 0.f;
    wv.y = (vy0 && vx1) ? hy * lx * m : 0.f;
    wv.z = (vy1 && vx0) ? ly * hx * m : 0.f;
    wv.w = (vy1 && vx1) ? ly * lx * m : 0.f;
    int y0c = min(max(y0, 0), HH - 1), y1c = min(max(y1, 0), HH - 1);
    int x0c = min(max(x0, 0), WW - 1), x1c = min(max(x1, 0), WW - 1);
    int4 iv;                              // uint4-unit indices within batch plane
    iv.x = (y0c * WW + x0c) * 16;
    iv.y = (y0c * WW + x1c) * 16;
    iv.z = (y1c * WW + x0c) * 16;
    iv.w = (y1c * WW + x1c) * 16;
    g_bw[idx] = wv;
    g_bi[idx] = iv;
}

// ============================================================
// 5) Deformable conv: fp16 gather -> fp32 interp -> fp16 MMA
//    CTA: M=128 px x N=128 oc; 18 chunks of 64 c.
//    dyn smem: As[128*SA] + Bs[2][128*SA] = 55296 B
// ============================================================
__global__ __launch_bounds__(256, 2)
void deform_mma(const float* __restrict__ bias,
                float* __restrict__ out) {
    extern __shared__ uint32_t dsm[];
    uint32_t* As = dsm;                    // 128*SA words
    uint32_t* Bs = dsm + 128 * SA;         // 2 x 128*SA words
    uint32_t bs_base = smem_u32(Bs);

    int tid = threadIdx.x;
    int wid = tid >> 5, lane = tid & 31;
    int g = lane >> 2, t = lane & 3;
    int b   = blockIdx.z;
    int ho0 = blockIdx.y * 4;
    int wo0 = blockIdx.x * 32;

    int wpx0 = (wid & 3) * 32;
    int woc0 = (wid >> 2) * 64;

    int gp = tid >> 3;
    int gc = lane & 7;

    float acc[2][8][4];
#pragma unroll
    for (int mt = 0; mt < 2; mt++)
#pragma unroll
        for (int nt = 0; nt < 8; nt++)
#pragma unroll
            for (int r = 0; r < 4; r++) acc[mt][nt][r] = 0.f;

    int pixp[4];
#pragma unroll
    for (int pass = 0; pass < 4; pass++) {
        int p = pass * 32 + gp;
        pixp[pass] = (ho0 + (p >> 5)) * WW + wo0 + (p & 31);
    }

    const uint4* xh = g_xh + (size_t)b * PLANE * 16;
    int pbase = (b * K2) * PLANE;

    // prologue: cp.async B chunk 0 (128 oc x 32 words = 16KB), 4 x 16B per thread
    {
        const uint32_t* wsrc = g_wt16;
#pragma unroll
        for (int k = 0; k < 4; k++) {
            int lin = tid + k * 256;
            int oc = lin >> 3, jj = (lin & 7) * 4;
            CP_ASYNC16(bs_base + (oc * SA + jj) * 4, wsrc + oc * 32 + jj);
        }
        CP_COMMIT();
    }

    for (int tap = 0; tap < 9; ++tap) {
        int4 iv4[4];
        float4 wv4[4];
#pragma unroll
        for (int pass = 0; pass < 4; pass++) {
            iv4[pass] = g_bi[pbase + tap * PLANE + pixp[pass]];
            wv4[pass] = g_bw[pbase + tap * PLANE + pixp[pass]];
        }

#pragma unroll 1
        for (int cq = 0; cq < 2; ++cq) {
            int chunk = tap * 2 + cq;
            __syncthreads();

            if (chunk < 17) {
                const uint32_t* wsrc = g_wt16 + (size_t)(chunk + 1) * 4096;
                uint32_t dstb = bs_base + (((chunk + 1) & 1) * 128 * SA) * 4;
#pragma unroll
                for (int k = 0; k < 4; k++) {
                    int lin = tid + k * 256;
                    int oc = lin >> 3, jj = (lin & 7) * 4;
                    CP_ASYNC16(dstb + (oc * SA + jj) * 4, wsrc + oc * 32 + jj);
                }
                CP_COMMIT();
            }

            // gather 4 corners (8 halves each) + fp32 interp -> fp16 pairs
#pragma unroll
            for (int pass = 0; pass < 4; pass++) {
                float4 wv = wv4[pass];
                int4 iv = iv4[pass];
                int cc = cq * 8 + gc;
                uint4 u00 = xh[iv.x + cc];
                uint4 u01 = xh[iv.y + cc];
                uint4 u10 = xh[iv.z + cc];
                uint4 u11 = xh[iv.w + cc];
                uint32_t pk[4];
#pragma unroll
                for (int j = 0; j < 4; j++) {
                    float2 f00 = __half22float2(*(__half2*)&((uint32_t*)&u00)[j]);
                    float2 f01 = __half22float2(*(__half2*)&((uint32_t*)&u01)[j]);
                    float2 f10 = __half22float2(*(__half2*)&((uint32_t*)&u10)[j]);
                    float2 f11 = __half22float2(*(__half2*)&((uint32_t*)&u11)[j]);
                    float rl = wv.x * f00.x + wv.y * f01.x + wv.z * f10.x + wv.w * f11.x;
                    float rh = wv.x * f00.y + wv.y * f01.y + wv.z * f10.y + wv.w * f11.y;
                    pk[j] = pack_h2(rl, rh);
                }
                *(uint4*)&As[(pass * 32 + gp) * SA + gc * 4] = *(uint4*)pk;
            }

            if (chunk < 17) { CP_WAIT(1); } else { CP_WAIT(0); }
            __syncthreads();

            const uint32_t* bsc = Bs + (chunk & 1) * 128 * SA;
#pragma unroll
            for (int ks = 0; ks < 4; ks++) {
                int c0 = ks * 8 + t;
                uint32_t afrag[2][4];
#pragma unroll
                for (int mt = 0; mt < 2; mt++) {
                    int row = wpx0 + mt * 16 + g;
                    afrag[mt][0] = As[row * SA + c0];
                    afrag[mt][1] = As[(row + 8) * SA + c0];
                    afrag[mt][2] = As[row * SA + c0 + 4];
                    afrag[mt][3] = As[(row + 8) * SA + c0 + 4];
                }
                uint32_t bfrag[8][2];
#pragma unroll
                for (int nt = 0; nt < 8; nt++) {
                    int oc = woc0 + nt * 8 + g;
                    bfrag[nt][0] = bsc[oc * SA + c0];
                    bfrag[nt][1] = bsc[oc * SA + c0 + 4];
                }
#pragma unroll
                for (int mt = 0; mt < 2; mt++)
#pragma unroll
                    for (int nt = 0; nt < 8; nt++)
                        mma_f16(acc[mt][nt], afrag[mt], bfrag[nt]);
            }
        }
    }

    // epilogue: acc -> out (NCHW) + bias
    int e_ho = ho0 + (wid & 3);
    float* ob = out + ((size_t)b * COUT) * PLANE + (size_t)e_ho * WW + wo0;
#pragma unroll
    for (int nt = 0; nt < 8; nt++) {
        int oc0 = woc0 + nt * 8 + 2 * t;
        float b0 = __ldg(&bias[oc0]);
        float b1 = __ldg(&bias[oc0 + 1]);
#pragma unroll
        for (int mt = 0; mt < 2; mt++) {
            int wo_a = mt * 16 + g;
            float* r0 = ob + (size_t)oc0 * PLANE + wo_a;
            float* r1 = ob + (size_t)(oc0 + 1) * PLANE + wo_a;
            r0[0] = acc[mt][nt][0] + b0;
            r1[0] = acc[mt][nt][1] + b1;
            r0[8] = acc[mt][nt][2] + b0;
            r1[8] = acc[mt][nt][3] + b1;
        }
    }
}

// ============================================================
// launch
// ============================================================
extern "C" void kernel_launch(void* const* d_in, const int* in_sizes, int n_in,
                              void* d_out, int out_size) {
    (void)in_sizes; (void)n_in; (void)out_size;
    const float* x      = (const float*)d_in[0];
    const float* weight = (const float*)d_in[1];
    const float* bias   = (const float*)d_in[2];
    const float* w_off  = (const float*)d_in[3];

    float* out = (float*)d_out;
    float* off = out + OUT_MAIN_ELEMS;   // second output: offsets [B,18,H,W]

    const int DSMEM = (128 * SA * 3) * 4;   // 55296 B
    cudaFuncSetAttribute(deform_mma, cudaFuncAttributeMaxDynamicSharedMemorySize, DSMEM);

    transpose_to_fp16<<<dim3(WW / 32, CIN / 32, BB * HH), dim3(32, 8)>>>(x);
    prep_weights<<<(18 * 128 * 32 + 255) / 256, 256>>>(weight, w_off);
    offset_mma<<<(BB * PLANE) / 256, 256>>>(off);
    prep_bilinear<<<(BB * K2 * PLANE + 255) / 256, 256>>>(off);
    deform_mma<<<dim3(WW / 32, HH / 4, BB), 256, DSMEM>>>(bias, out);
}

// round 10
// speedup vs baseline: 1.9921x; 1.0006x over previous
#include <cuda_runtime.h>
#include <cuda_fp16.h>
#include <math.h>
#include <stdint.h>

#define BB   4
#define CIN  128
#define COUT 128
#define HH   96
#define WW   96
#define K2   9

#define OUT_MAIN_ELEMS (BB*COUT*HH*WW)   // 4718592
#define PLANE (HH*WW)                    // 9216

#define SA 36   // smem row stride (words): 32 data + 4 pad (conflict-free)

// ---- device scratch (no allocations allowed) ----
__device__ uint4    g_xh[BB*PLANE*16];       // x in NHWC fp16: 16 uint4 per px
__device__ float    g_mask[BB*K2*PLANE];     // sigmoid(om[18:27])*2
__device__ uint32_t g_wt16[18*128*32];       // fp16x2 main weights: [chunk64][oc128][cpair32]
__device__ uint32_t g_wofft16[18*32*32];     // fp16x2 offset weights
__device__ float4   g_bw[BB*K2*PLANE];       // per (b,tap,px): 4 corner weights (mask folded)
__device__ int4     g_bi[BB*K2*PLANE];       // per (b,tap,px): 4 corner base idx (uint4 units)

__device__ __forceinline__ uint32_t pack_h2(float lo, float hi) {
    __half2 h = __floats2half2_rn(lo, hi);
    return *(uint32_t*)&h;
}
__device__ __forceinline__ uint32_t smem_u32(const void* p) {
    uint32_t a;
    asm("{ .reg .u64 t; cvta.to.shared.u64 t, %1; cvt.u32.u64 %0, t; }" : "=r"(a) : "l"(p));
    return a;
}
__device__ __forceinline__ void mma_f16(float d[4], const uint32_t a[4], const uint32_t b[2]) {
    asm volatile(
        "mma.sync.aligned.m16n8k16.row.col.f32.f16.f16.f32 "
        "{%0,%1,%2,%3}, {%4,%5,%6,%7}, {%8,%9}, {%0,%1,%2,%3};"
        : "+f"(d[0]), "+f"(d[1]), "+f"(d[2]), "+f"(d[3])
        : "r"(a[0]), "r"(a[1]), "r"(a[2]), "r"(a[3]), "r"(b[0]), "r"(b[1]));
}
#define CP_ASYNC16(dst, src) \
    asm volatile("cp.async.cg.shared.global [%0], [%1], 16;" :: "r"(dst), "l"(src) : "memory")
#define CP_COMMIT() asm volatile("cp.async.commit_group;" ::: "memory")
#define CP_WAIT(n)  asm volatile("cp.async.wait_group %0;" :: "n"(n) : "memory")

// ============================================================
// 1) NCHW fp32 -> NHWC fp16
// ============================================================
__global__ void transpose_to_fp16(const float* __restrict__ x) {
    __shared__ float t[32][33];
    int w0 = blockIdx.x * 32;
    int c0 = blockIdx.y * 32;
    int bh = blockIdx.z;
    int b = bh / HH;
    int h = bh % HH;
    const float* xb = x + (size_t)b * CIN * HH * WW;
#pragma unroll
    for (int i = 0; i < 32; i += 8) {
        int c = c0 + threadIdx.y + i;
        t[threadIdx.y + i][threadIdx.x] = xb[((size_t)c * HH + h) * WW + w0 + threadIdx.x];
    }
    __syncthreads();
    __half* xh = (__half*)g_xh + ((size_t)b * PLANE + h * WW) * CIN;
#pragma unroll
    for (int i = 0; i < 32; i += 8) {
        int w = w0 + threadIdx.y + i;
        xh[(size_t)w * CIN + c0 + threadIdx.x] = __float2half_rn(t[threadIdx.x][threadIdx.y + i]);
    }
}

// ============================================================
// 2) Weight prep -> fp16x2, 64-channel chunk layouts
// ============================================================
__global__ void prep_weights(const float* __restrict__ weight,
                             const float* __restrict__ w_off) {
    int idx = blockIdx.x * 256 + threadIdx.x;
    if (idx < 18 * 128 * 32) {
        int chunk = idx >> 12;
        int r     = idx & 4095;
        int oc    = r >> 5;
        int j     = r & 31;
        int c     = (chunk & 1) * 64 + 2 * j;
        int tap   = chunk >> 1;
        float w0 = weight[((size_t)oc * CIN + c) * K2 + tap];
        float w1 = weight[((size_t)oc * CIN + c + 1) * K2 + tap];
        g_wt16[idx] = pack_h2(w0, w1);
    }
    if (idx < 18 * 32 * 32) {
        int chunk = idx >> 10;
        int r     = idx & 1023;
        int oc    = r >> 5;
        int j     = r & 31;
        int c     = (chunk & 1) * 64 + 2 * j;
        int tap   = chunk >> 1;
        float w0 = 0.f, w1 = 0.f;
        if (oc < 27) {
            w0 = w_off[((size_t)oc * CIN + c) * K2 + tap];
            w1 = w_off[((size_t)oc * CIN + c + 1) * K2 + tap];
        }
        g_wofft16[idx] = pack_h2(w0, w1);
    }
}

// ============================================================
// 3) Offset/mask conv via fp16 MMA (unchanged from R9)
// ============================================================
__global__ __launch_bounds__(256)
void offset_mma(float* __restrict__ out_off) {
    __shared__ uint32_t As[256 * SA];
    __shared__ uint32_t Bs[32 * SA];

    int tid = threadIdx.x;
    int wid = tid >> 5, lane = tid & 31;
    int g = lane >> 2, t = lane & 3;
    int pix0 = blockIdx.x * 256;
    int wpx0 = wid * 32;

    int gp = tid >> 3;
    int gc = lane & 7;

    int pp_b[8], pp_h[8], pp_w[8];
#pragma unroll
    for (int pass = 0; pass < 8; pass++) {
        int pixg = pix0 + pass * 32 + gp;
        pp_b[pass] = pixg / PLANE;
        int pr = pixg % PLANE;
        pp_h[pass] = pr / WW;
        pp_w[pass] = pr % WW;
    }

    float acc[2][4][4];
#pragma unroll
    for (int mt = 0; mt < 2; mt++)
#pragma unroll
        for (int nt = 0; nt < 4; nt++)
#pragma unroll
            for (int r = 0; r < 4; r++) acc[mt][nt][r] = 0.f;

    for (int chunk = 0; chunk < 18; ++chunk) {
        int tap = chunk >> 1, cq = chunk & 1;
        int ki = tap / 3, kj = tap % 3;
        __syncthreads();

        {
            const uint32_t* bs = g_wofft16 + (size_t)chunk * 1024;
            int oc = tid >> 3, jw = (tid & 7) * 4;
            *(uint4*)&Bs[oc * SA + jw] = *(const uint4*)&bs[oc * 32 + jw];
        }

#pragma unroll
        for (int pass = 0; pass < 8; pass++) {
            int y = pp_h[pass] + ki - 1, x = pp_w[pass] + kj - 1;
            bool ok = (y >= 0) && (y < HH) && (x >= 0) && (x < WW);
            uint4 v = make_uint4(0u, 0u, 0u, 0u);
            if (ok) v = g_xh[((size_t)pp_b[pass] * PLANE + y * WW + x) * 16 + cq * 8 + gc];
            *(uint4*)&As[(pass * 32 + gp) * SA + gc * 4] = v;
        }
        __syncthreads();

#pragma unroll
        for (int ks = 0; ks < 4; ks++) {
            int c0 = ks * 8 + t;
            uint32_t afrag[2][4];
#pragma unroll
            for (int mt = 0; mt < 2; mt++) {
                int row = wpx0 + mt * 16 + g;
                afrag[mt][0] = As[row * SA + c0];
                afrag[mt][1] = As[(row + 8) * SA + c0];
                afrag[mt][2] = As[row * SA + c0 + 4];
                afrag[mt][3] = As[(row + 8) * SA + c0 + 4];
            }
            uint32_t bfrag[4][2];
#pragma unroll
            for (int nt = 0; nt < 4; nt++) {
                int oc = nt * 8 + g;
                bfrag[nt][0] = Bs[oc * SA + c0];
                bfrag[nt][1] = Bs[oc * SA + c0 + 4];
            }
#pragma unroll
            for (int mt = 0; mt < 2; mt++)
#pragma unroll
                for (int nt = 0; nt < 4; nt++)
                    mma_f16(acc[mt][nt], afrag[mt], bfrag[nt]);
        }
    }

#pragma unroll
    for (int nt = 0; nt < 4; nt++) {
        int oc0 = nt * 8 + 2 * t;
#pragma unroll
        for (int mt = 0; mt < 2; mt++) {
            int row = wpx0 + mt * 16 + g;
#pragma unroll
            for (int rr = 0; rr < 4; rr++) {
                int oc = oc0 + (rr & 1);
                int pixg = pix0 + row + (rr >> 1) * 8;
                float v = acc[mt][nt][rr];
                int b = pixg / PLANE;
                int pr = pixg % PLANE;
                if (oc < 18) {
                    out_off[((size_t)b * 18 + oc) * PLANE + pr] = v;
                } else if (oc < 27) {
                    g_mask[((size_t)b * 9 + (oc - 18)) * PLANE + pr] =
                        2.0f / (1.0f + expf(-v));
                }
            }
        }
    }
}

// ============================================================
// 4) Precompute bilinear params per (b, tap, px)
// ============================================================
__global__ void prep_bilinear(const float* __restrict__ off) {
    int idx = blockIdx.x * 256 + threadIdx.x;
    if (idx >= BB * K2 * PLANE) return;
    int b   = idx / (K2 * PLANE);
    int r   = idx % (K2 * PLANE);
    int tap = r / PLANE;
    int pix = r % PLANE;
    int h = pix / WW, w = pix % WW;

    float o1 = off[((size_t)b * 18 + tap) * PLANE + pix];
    float o2 = off[((size_t)b * 18 + 9 + tap) * PLANE + pix];
    float m  = g_mask[((size_t)b * 9 + tap) * PLANE + pix];

    int ki = tap / 3, kj = tap % 3;
    float py  = (float)(h - 1 + ki) + o1;
    float pxx = (float)(w - 1 + kj) + o2;
    float y0f = floorf(py), x0f = floorf(pxx);
    float ly = py - y0f, lx = pxx - x0f;
    float hy = 1.f - ly, hx = 1.f - lx;
    int y0 = (int)y0f, x0 = (int)x0f;
    int y1 = y0 + 1, x1 = x0 + 1;
    bool vy0 = (y0 >= 0) && (y0 < HH), vy1 = (y1 >= 0) && (y1 < HH);
    bool vx0 = (x0 >= 0) && (x0 < WW), vx1 = (x1 >= 0) && (x1 < WW);
    float4 wv;
    wv.x = (vy0 && vx0) ? hy * hx * m : 0.f;
    wv.y = (vy0 && vx1) ? hy * lx * m : 0.f;
    wv.z = (vy1 && vx0) ? ly * hx * m : 0.f;
    wv.w = (vy1 && vx1) ? ly * lx * m : 0.f;
    int y0c = min(max(y0, 0), HH - 1), y1c = min(max(y1, 0), HH - 1);
    int x0c = min(max(x0, 0), WW - 1), x1c = min(max(x1, 0), WW - 1);
    int4 iv;
    iv.x = (y0c * WW + x0c) * 16;
    iv.y = (y0c * WW + x1c) * 16;
    iv.z = (y1c * WW + x0c) * 16;
    iv.w = (y1c * WW + x1c) * 16;
    g_bw[idx] = wv;
    g_bi[idx] = iv;
}

// ============================================================
// 5) Deformable conv: CTA 256px x 128oc, warp tile 64px x 64oc.
//    18 chunks of 64 c. 144 CTAs = one wave on 148 SMs.
//    dyn smem: As[256*SA] + Bs[2][128*SA] = 73728 B
// ============================================================
__global__ __launch_bounds__(256, 1)
void deform_mma(const float* __restrict__ bias,
                float* __restrict__ out) {
    extern __shared__ uint32_t dsm[];
    uint32_t* As = dsm;                    // 256*SA words
    uint32_t* Bs = dsm + 256 * SA;         // 2 x 128*SA words
    uint32_t bs_base = smem_u32(Bs);

    int tid = threadIdx.x;
    int wid = tid >> 5, lane = tid & 31;
    int g = lane >> 2, t = lane & 3;
    int b   = blockIdx.z;
    int ho0 = blockIdx.y * 8;
    int wo0 = blockIdx.x * 32;

    int wpx0 = (wid & 3) * 64;             // warp px base (4 groups of 64)
    int woc0 = (wid >> 2) * 64;            // warp oc base (2 groups of 64)

    int gp = tid >> 3;                     // pixel slot within pass (0..31)
    int gc = tid & 7;                      // channel uint4 slot

    float acc[4][8][4];
#pragma unroll
    for (int mt = 0; mt < 4; mt++)
#pragma unroll
        for (int nt = 0; nt < 8; nt++)
#pragma unroll
            for (int r = 0; r < 4; r++) acc[mt][nt][r] = 0.f;

    const uint4* xh = g_xh + (size_t)b * PLANE * 16;
    int pbase = (b * K2) * PLANE;
    int mypix = wo0 + gp;                  // pass p pixel: (ho0+p)*WW + mypix

    // prologue: cp.async B chunk 0 (16KB), 4 x 16B per thread
    {
        const uint32_t* wsrc = g_wt16;
#pragma unroll
        for (int k = 0; k < 4; k++) {
            int lin = tid + k * 256;
            int oc = lin >> 3, jj = (lin & 7) * 4;
            CP_ASYNC16(bs_base + (oc * SA + jj) * 4, wsrc + oc * 32 + jj);
        }
        CP_COMMIT();
    }

    for (int tap = 0; tap < 9; ++tap) {
#pragma unroll 1
        for (int cq = 0; cq < 2; ++cq) {
            int chunk = tap * 2 + cq;
            __syncthreads();

            if (chunk < 17) {
                const uint32_t* wsrc = g_wt16 + (size_t)(chunk + 1) * 4096;
                uint32_t dstb = bs_base + (((chunk + 1) & 1) * 128 * SA) * 4;
#pragma unroll
                for (int k = 0; k < 4; k++) {
                    int lin = tid + k * 256;
                    int oc = lin >> 3, jj = (lin & 7) * 4;
                    CP_ASYNC16(dstb + (oc * SA + jj) * 4, wsrc + oc * 32 + jj);
                }
                CP_COMMIT();
            }

            // gather 256px x 64c in 8 passes of 32 px
#pragma unroll
            for (int pass = 0; pass < 8; pass++) {
                int pa = pbase + tap * PLANE + (ho0 + pass) * WW + mypix;
                float4 wv = g_bw[pa];
                int4 iv   = g_bi[pa];
                int cc = cq * 8 + gc;
                uint4 u00 = xh[iv.x + cc];
                uint4 u01 = xh[iv.y + cc];
                uint4 u10 = xh[iv.z + cc];
                uint4 u11 = xh[iv.w + cc];
                uint32_t pk[4];
#pragma unroll
                for (int j = 0; j < 4; j++) {
                    float2 f00 = __half22float2(*(__half2*)&((uint32_t*)&u00)[j]);
                    float2 f01 = __half22float2(*(__half2*)&((uint32_t*)&u01)[j]);
                    float2 f10 = __half22float2(*(__half2*)&((uint32_t*)&u10)[j]);
                    float2 f11 = __half22float2(*(__half2*)&((uint32_t*)&u11)[j]);
                    float rl = wv.x * f00.x + wv.y * f01.x + wv.z * f10.x + wv.w * f11.x;
                    float rh = wv.x * f00.y + wv.y * f01.y + wv.z * f10.y + wv.w * f11.y;
                    pk[j] = pack_h2(rl, rh);
                }
                *(uint4*)&As[(pass * 32 + gp) * SA + gc * 4] = *(uint4*)pk;
            }

            if (chunk < 17) { CP_WAIT(1); } else { CP_WAIT(0); }
            __syncthreads();

            const uint32_t* bsc = Bs + (chunk & 1) * 128 * SA;
#pragma unroll
            for (int ks = 0; ks < 4; ks++) {
                int c0 = ks * 8 + t;
                uint32_t afrag[4][4];
#pragma unroll
                for (int mt = 0; mt < 4; mt++) {
                    int row = wpx0 + mt * 16 + g;
                    afrag[mt][0] = As[row * SA + c0];
                    afrag[mt][1] = As[(row + 8) * SA + c0];
                    afrag[mt][2] = As[row * SA + c0 + 4];
                    afrag[mt][3] = As[(row + 8) * SA + c0 + 4];
                }
                uint32_t bfrag[8][2];
#pragma unroll
                for (int nt = 0; nt < 8; nt++) {
                    int oc = woc0 + nt * 8 + g;
                    bfrag[nt][0] = bsc[oc * SA + c0];
                    bfrag[nt][1] = bsc[oc * SA + c0 + 4];
                }
#pragma unroll
                for (int mt = 0; mt < 4; mt++)
#pragma unroll
                    for (int nt = 0; nt < 8; nt++)
                        mma_f16(acc[mt][nt], afrag[mt], bfrag[nt]);
            }
        }
    }

    // epilogue: acc -> out (NCHW) + bias
    // px = wpx0 + mt*16 + g (+8 for d2/d3): ho = ho0 + (px>>5), wo = wo0 + (px&31)
    float* outb = out + (size_t)b * COUT * PLANE;
#pragma unroll
    for (int nt = 0; nt < 8; nt++) {
        int oc0 = woc0 + nt * 8 + 2 * t;
        float b0 = __ldg(&bias[oc0]);
        float b1 = __ldg(&bias[oc0 + 1]);
#pragma unroll
        for (int mt = 0; mt < 4; mt++) {
            int px = wpx0 + mt * 16 + g;
            int e_ho = ho0 + (px >> 5);
            int e_wo = wo0 + (px & 31);
            float* r0 = outb + (size_t)oc0 * PLANE + e_ho * WW + e_wo;
            float* r1 = outb + (size_t)(oc0 + 1) * PLANE + e_ho * WW + e_wo;
            r0[0] = acc[mt][nt][0] + b0;
            r1[0] = acc[mt][nt][1] + b1;
            r0[8] = acc[mt][nt][2] + b0;
            r1[8] = acc[mt][nt][3] + b1;
        }
    }
}

// ============================================================
// launch
// ============================================================
extern "C" void kernel_launch(void* const* d_in, const int* in_sizes, int n_in,
                              void* d_out, int out_size) {
    (void)in_sizes; (void)n_in; (void)out_size;
    const float* x      = (const float*)d_in[0];
    const float* weight = (const float*)d_in[1];
    const float* bias   = (const float*)d_in[2];
    const float* w_off  = (const float*)d_in[3];

    float* out = (float*)d_out;
    float* off = out + OUT_MAIN_ELEMS;   // second output: offsets [B,18,H,W]

    const int DSMEM = (256 * SA + 2 * 128 * SA) * 4;   // 73728 B
    cudaFuncSetAttribute(deform_mma, cudaFuncAttributeMaxDynamicSharedMemorySize, DSMEM);

    transpose_to_fp16<<<dim3(WW / 32, CIN / 32, BB * HH), dim3(32, 8)>>>(x);
    prep_weights<<<(18 * 128 * 32 + 255) / 256, 256>>>(weight, w_off);
    offset_mma<<<(BB * PLANE) / 256, 256>>>(off);
    prep_bilinear<<<(BB * K2 * PLANE + 255) / 256, 256>>>(off);
    deform_mma<<<dim3(WW / 32, HH / 8, BB), 256, DSMEM>>>(bias, out);
}

// round 11
// speedup vs baseline: 2.0406x; 1.0244x over previous
#include <cuda_runtime.h>
#include <cuda_fp16.h>
#include <math.h>
#include <stdint.h>

#define BB   4
#define CIN  128
#define COUT 128
#define HH   96
#define WW   96
#define K2   9

#define OUT_MAIN_ELEMS (BB*COUT*HH*WW)   // 4718592
#define PLANE (HH*WW)                    // 9216

#define SA 36   // smem row stride (words): 32 data + 4 pad (conflict-free)

// ---- device scratch (no allocations allowed) ----
__device__ uint4    g_xh[BB*PLANE*16];       // x in NHWC fp16: 16 uint4 per px
__device__ float    g_mask[BB*K2*PLANE];     // sigmoid(om[18:27])*2
__device__ uint32_t g_wt16[18*128*32];       // fp16x2 main weights: [chunk64][oc128][cpair32]
__device__ uint32_t g_wofft16[18*32*32];     // fp16x2 offset weights
__device__ float4   g_bw[BB*K2*PLANE];       // per (b,tap,px): 4 corner weights (mask folded)
__device__ int4     g_bi[BB*K2*PLANE];       // per (b,tap,px): 4 corner base idx (uint4 units)

__device__ __forceinline__ uint32_t pack_h2(float lo, float hi) {
    __half2 h = __floats2half2_rn(lo, hi);
    return *(uint32_t*)&h;
}
__device__ __forceinline__ uint32_t smem_u32(const void* p) {
    uint32_t a;
    asm("{ .reg .u64 t; cvta.to.shared.u64 t, %1; cvt.u32.u64 %0, t; }" : "=r"(a) : "l"(p));
    return a;
}
__device__ __forceinline__ void mma_f16(float d[4], const uint32_t a[4], const uint32_t b[2]) {
    asm volatile(
        "mma.sync.aligned.m16n8k16.row.col.f32.f16.f16.f32 "
        "{%0,%1,%2,%3}, {%4,%5,%6,%7}, {%8,%9}, {%0,%1,%2,%3};"
        : "+f"(d[0]), "+f"(d[1]), "+f"(d[2]), "+f"(d[3])
        : "r"(a[0]), "r"(a[1]), "r"(a[2]), "r"(a[3]), "r"(b[0]), "r"(b[1]));
}
#define CP_ASYNC16(dst, src) \
    asm volatile("cp.async.cg.shared.global [%0], [%1], 16;" :: "r"(dst), "l"(src) : "memory")
#define CP_ASYNC16Z(dst, src, sz) \
    asm volatile("cp.async.cg.shared.global [%0], [%1], 16, %2;" :: "r"(dst), "l"(src), "r"(sz) : "memory")
#define CP_COMMIT() asm volatile("cp.async.commit_group;" ::: "memory")
#define CP_WAIT(n)  asm volatile("cp.async.wait_group %0;" :: "n"(n) : "memory")

// ============================================================
// 1) NCHW fp32 -> NHWC fp16
// ============================================================
__global__ void transpose_to_fp16(const float* __restrict__ x) {
    __shared__ float t[32][33];
    int w0 = blockIdx.x * 32;
    int c0 = blockIdx.y * 32;
    int bh = blockIdx.z;
    int b = bh / HH;
    int h = bh % HH;
    const float* xb = x + (size_t)b * CIN * HH * WW;
#pragma unroll
    for (int i = 0; i < 32; i += 8) {
        int c = c0 + threadIdx.y + i;
        t[threadIdx.y + i][threadIdx.x] = xb[((size_t)c * HH + h) * WW + w0 + threadIdx.x];
    }
    __syncthreads();
    __half* xh = (__half*)g_xh + ((size_t)b * PLANE + h * WW) * CIN;
#pragma unroll
    for (int i = 0; i < 32; i += 8) {
        int w = w0 + threadIdx.y + i;
        xh[(size_t)w * CIN + c0 + threadIdx.x] = __float2half_rn(t[threadIdx.x][threadIdx.y + i]);
    }
}

// ============================================================
// 2) Weight prep -> fp16x2, 64-channel chunk layouts
// ============================================================
__global__ void prep_weights(const float* __restrict__ weight,
                             const float* __restrict__ w_off) {
    int idx = blockIdx.x * 256 + threadIdx.x;
    if (idx < 18 * 128 * 32) {
        int chunk = idx >> 12;
        int r     = idx & 4095;
        int oc    = r >> 5;
        int j     = r & 31;
        int c     = (chunk & 1) * 64 + 2 * j;
        int tap   = chunk >> 1;
        float w0 = weight[((size_t)oc * CIN + c) * K2 + tap];
        float w1 = weight[((size_t)oc * CIN + c + 1) * K2 + tap];
        g_wt16[idx] = pack_h2(w0, w1);
    }
    if (idx < 18 * 32 * 32) {
        int chunk = idx >> 10;
        int r     = idx & 1023;
        int oc    = r >> 5;
        int j     = r & 31;
        int c     = (chunk & 1) * 64 + 2 * j;
        int tap   = chunk >> 1;
        float w0 = 0.f, w1 = 0.f;
        if (oc < 27) {
            w0 = w_off[((size_t)oc * CIN + c) * K2 + tap];
            w1 = w_off[((size_t)oc * CIN + c + 1) * K2 + tap];
        }
        g_wofft16[idx] = pack_h2(w0, w1);
    }
}

// ============================================================
// 3) Offset/mask conv via fp16 MMA, 3-stage cp.async pipeline
//    CTA: 256 px x 32 oc; 18 chunks of 64 c; grid 144 (one wave)
//    dyn smem: 3*(256*SA) A + 3*(32*SA) B words = 124416 B
// ============================================================
__global__ __launch_bounds__(256, 1)
void offset_mma(float* __restrict__ out_off) {
    extern __shared__ uint32_t osm[];
    uint32_t as_base = smem_u32(osm);
    uint32_t bs_base = as_base + 3 * 256 * SA * 4;

    int tid = threadIdx.x;
    int wid = tid >> 5, lane = tid & 31;
    int g = lane >> 2, t = lane & 3;
    int pix0 = blockIdx.x * 256;
    int wpx0 = wid * 32;

    int gp = tid >> 3;
    int gc = tid & 7;

    int pp_b[8], pp_h[8], pp_w[8];
#pragma unroll
    for (int pass = 0; pass < 8; pass++) {
        int pixg = pix0 + pass * 32 + gp;
        pp_b[pass] = pixg / PLANE;
        int pr = pixg % PLANE;
        pp_h[pass] = pr / WW;
        pp_w[pass] = pr % WW;
    }

    float acc[2][4][4];
#pragma unroll
    for (int mt = 0; mt < 2; mt++)
#pragma unroll
        for (int nt = 0; nt < 4; nt++)
#pragma unroll
            for (int r = 0; r < 4; r++) acc[mt][nt][r] = 0.f;

    // stage issue: chunk cidx -> ring stage s
#define OFF_STAGE(cidx, s) do { \
        int tap_ = (cidx) >> 1, cq_ = (cidx) & 1; \
        int ki_ = tap_ / 3, kj_ = tap_ % 3; \
        { int oc_ = tid >> 3, jw_ = (tid & 7) * 4; \
          CP_ASYNC16(bs_base + ((s) * 32 * SA + oc_ * SA + jw_) * 4, \
                     g_wofft16 + (size_t)(cidx) * 1024 + oc_ * 32 + jw_); } \
        _Pragma("unroll") \
        for (int pass_ = 0; pass_ < 8; pass_++) { \
            int y_ = pp_h[pass_] + ki_ - 1, x_ = pp_w[pass_] + kj_ - 1; \
            bool ok_ = (y_ >= 0) && (y_ < HH) && (x_ >= 0) && (x_ < WW); \
            int yc_ = min(max(y_, 0), HH - 1), xc_ = min(max(x_, 0), WW - 1); \
            const uint4* src_ = g_xh + ((size_t)pp_b[pass_] * PLANE + yc_ * WW + xc_) * 16 + cq_ * 8 + gc; \
            uint32_t dst_ = as_base + ((s) * 256 * SA + (pass_ * 32 + gp) * SA + gc * 4) * 4; \
            CP_ASYNC16Z(dst_, src_, ok_ ? 16 : 0); \
        } \
        CP_COMMIT(); \
    } while (0)

    OFF_STAGE(0, 0);
    OFF_STAGE(1, 1);

    for (int chunk = 0; chunk < 18; ++chunk) {
        if (chunk >= 16) { CP_WAIT(0); } else { CP_WAIT(1); }
        __syncthreads();
        if (chunk < 16) {
            int s = (chunk + 2) % 3;
            OFF_STAGE(chunk + 2, s);
        }

        const uint32_t* Asx = osm + (chunk % 3) * 256 * SA;
        const uint32_t* Bsx = osm + 3 * 256 * SA + (chunk % 3) * 32 * SA;
#pragma unroll
        for (int ks = 0; ks < 4; ks++) {
            int c0 = ks * 8 + t;
            uint32_t afrag[2][4];
#pragma unroll
            for (int mt = 0; mt < 2; mt++) {
                int row = wpx0 + mt * 16 + g;
                afrag[mt][0] = Asx[row * SA + c0];
                afrag[mt][1] = Asx[(row + 8) * SA + c0];
                afrag[mt][2] = Asx[row * SA + c0 + 4];
                afrag[mt][3] = Asx[(row + 8) * SA + c0 + 4];
            }
            uint32_t bfrag[4][2];
#pragma unroll
            for (int nt = 0; nt < 4; nt++) {
                int oc = nt * 8 + g;
                bfrag[nt][0] = Bsx[oc * SA + c0];
                bfrag[nt][1] = Bsx[oc * SA + c0 + 4];
            }
#pragma unroll
            for (int mt = 0; mt < 2; mt++)
#pragma unroll
                for (int nt = 0; nt < 4; nt++)
                    mma_f16(acc[mt][nt], afrag[mt], bfrag[nt]);
        }
    }

#pragma unroll
    for (int nt = 0; nt < 4; nt++) {
        int oc0 = nt * 8 + 2 * t;
#pragma unroll
        for (int mt = 0; mt < 2; mt++) {
            int row = wpx0 + mt * 16 + g;
#pragma unroll
            for (int rr = 0; rr < 4; rr++) {
                int oc = oc0 + (rr & 1);
                int pixg = pix0 + row + (rr >> 1) * 8;
                float v = acc[mt][nt][rr];
                int b = pixg / PLANE;
                int pr = pixg % PLANE;
                if (oc < 18) {
                    out_off[((size_t)b * 18 + oc) * PLANE + pr] = v;
                } else if (oc < 27) {
                    g_mask[((size_t)b * 9 + (oc - 18)) * PLANE + pr] =
                        2.0f / (1.0f + expf(-v));
                }
            }
        }
    }
#undef OFF_STAGE
}

// ============================================================
// 4) Precompute bilinear params per (b, tap, px)
// ============================================================
__global__ void prep_bilinear(const float* __restrict__ off) {
    int idx = blockIdx.x * 256 + threadIdx.x;
    if (idx >= BB * K2 * PLANE) return;
    int b   = idx / (K2 * PLANE);
    int r   = idx % (K2 * PLANE);
    int tap = r / PLANE;
    int pix = r % PLANE;
    int h = pix / WW, w = pix % WW;

    float o1 = off[((size_t)b * 18 + tap) * PLANE + pix];
    float o2 = off[((size_t)b * 18 + 9 + tap) * PLANE + pix];
    float m  = g_mask[((size_t)b * 9 + tap) * PLANE + pix];

    int ki = tap / 3, kj = tap % 3;
    float py  = (float)(h - 1 + ki) + o1;
    float pxx = (float)(w - 1 + kj) + o2;
    float y0f = floorf(py), x0f = floorf(pxx);
    float ly = py - y0f, lx = pxx - x0f;
    float hy = 1.f - ly, hx = 1.f - lx;
    int y0 = (int)y0f, x0 = (int)x0f;
    int y1 = y0 + 1, x1 = x0 + 1;
    bool vy0 = (y0 >= 0) && (y0 < HH), vy1 = (y1 >= 0) && (y1 < HH);
    bool vx0 = (x0 >= 0) && (x0 < WW), vx1 = (x1 >= 0) && (x1 < WW);
    float4 wv;
    wv.x = (vy0 && vx0) ? hy * hx * m : 0.f;
    wv.y = (vy0 && vx1) ? hy * lx * m : 0.f;
    wv.z = (vy1 && vx0) ? ly * hx * m : 0.f;
    wv.w = (vy1 && vx1) ? ly * lx * m : 0.f;
    int y0c = min(max(y0, 0), HH - 1), y1c = min(max(y1, 0), HH - 1);
    int x0c = min(max(x0, 0), WW - 1), x1c = min(max(x1, 0), WW - 1);
    int4 iv;
    iv.x = (y0c * WW + x0c) * 16;
    iv.y = (y0c * WW + x1c) * 16;
    iv.z = (y1c * WW + x0c) * 16;
    iv.w = (y1c * WW + x1c) * 16;
    g_bw[idx] = wv;
    g_bi[idx] = iv;
}

// ============================================================
// 5) Deformable conv, software-pipelined:
//    iter c: [prefetch corner LDGs for c+1] -> MMA(c) -> interp+STS(c+1)
//    CTA 128px x 128oc; 18 chunks of 64 c; As/Bs double-buffered.
//    dyn smem: 2*(128*SA) + 2*(128*SA) words = 73728 B
// ============================================================
__global__ __launch_bounds__(256, 1)
void deform_mma(const float* __restrict__ bias,
                float* __restrict__ out) {
    extern __shared__ uint32_t dsm[];
    uint32_t* As = dsm;                     // 2 x 128*SA
    uint32_t* Bs = dsm + 2 * 128 * SA;      // 2 x 128*SA
    uint32_t bs_base = smem_u32(Bs);

    int tid = threadIdx.x;
    int wid = tid >> 5, lane = tid & 31;
    int g = lane >> 2, t = lane & 3;
    int b   = blockIdx.z;
    int ho0 = blockIdx.y * 4;
    int wo0 = blockIdx.x * 32;

    int wpx0 = (wid & 3) * 32;
    int woc0 = (wid >> 2) * 64;

    int gp = tid >> 3;
    int gc = tid & 7;

    float acc[2][8][4];
#pragma unroll
    for (int mt = 0; mt < 2; mt++)
#pragma unroll
        for (int nt = 0; nt < 8; nt++)
#pragma unroll
            for (int r = 0; r < 4; r++) acc[mt][nt][r] = 0.f;

    int pixp[4];
#pragma unroll
    for (int pass = 0; pass < 4; pass++) {
        int p = pass * 32 + gp;
        pixp[pass] = (ho0 + (p >> 5)) * WW + wo0 + (p & 31);
    }

    const uint4* xh = g_xh + (size_t)b * PLANE * 16;
    int pbase = (b * K2) * PLANE;

    int4  iv4[4];      // cached per tap
    uint4 u[4][4];     // prefetched corners for "next" chunk (pass x corner)

    // ---- prologue: B(0) via cp.async; corners chunk 0; interp -> As[0] ----
    {
#pragma unroll
        for (int k = 0; k < 4; k++) {
            int lin = tid + k * 256;
            int oc = lin >> 3, jj = (lin & 7) * 4;
            CP_ASYNC16(bs_base + (oc * SA + jj) * 4, g_wt16 + oc * 32 + jj);
        }
        CP_COMMIT();
    }
#pragma unroll
    for (int pass = 0; pass < 4; pass++)
        iv4[pass] = g_bi[pbase + 0 * PLANE + pixp[pass]];
#pragma unroll
    for (int pass = 0; pass < 4; pass++) {
        int4 iv = iv4[pass];
        u[pass][0] = xh[iv.x + gc];
        u[pass][1] = xh[iv.y + gc];
        u[pass][2] = xh[iv.z + gc];
        u[pass][3] = xh[iv.w + gc];
    }
#pragma unroll
    for (int pass = 0; pass < 4; pass++) {
        float4 wv = g_bw[pbase + 0 * PLANE + pixp[pass]];
        uint32_t pk[4];
#pragma unroll
        for (int j = 0; j < 4; j++) {
            float2 f00 = __half22float2(*(__half2*)&((uint32_t*)&u[pass][0])[j]);
            float2 f01 = __half22float2(*(__half2*)&((uint32_t*)&u[pass][1])[j]);
            float2 f10 = __half22float2(*(__half2*)&((uint32_t*)&u[pass][2])[j]);
            float2 f11 = __half22float2(*(__half2*)&((uint32_t*)&u[pass][3])[j]);
            float rl = wv.x * f00.x + wv.y * f01.x + wv.z * f10.x + wv.w * f11.x;
            float rh = wv.x * f00.y + wv.y * f01.y + wv.z * f10.y + wv.w * f11.y;
            pk[j] = pack_h2(rl, rh);
        }
        *(uint4*)&As[(pass * 32 + gp) * SA + gc * 4] = *(uint4*)pk;
    }

    // ---- main loop ----
#pragma unroll 1
    for (int c = 0; c < 18; ++c) {
        CP_WAIT(0);             // B(c) landed
        __syncthreads();        // As[c&1], Bs[c&1] visible; prev MMA done

        if (c < 17) {
            // stream B(c+1)
#pragma unroll
            for (int k = 0; k < 4; k++) {
                int lin = tid + k * 256;
                int oc = lin >> 3, jj = (lin & 7) * 4;
                CP_ASYNC16(bs_base + (((c + 1) & 1) * 128 * SA + oc * SA + jj) * 4,
                           g_wt16 + (size_t)(c + 1) * 4096 + oc * 32 + jj);
            }
            CP_COMMIT();
            // prefetch corners for chunk c+1 into registers
            int ntap = (c + 1) >> 1, ncq = (c + 1) & 1;
            if (ncq == 0) {
#pragma unroll
                for (int pass = 0; pass < 4; pass++)
                    iv4[pass] = g_bi[pbase + ntap * PLANE + pixp[pass]];
            }
            int cc = ncq * 8 + gc;
#pragma unroll
            for (int pass = 0; pass < 4; pass++) {
                int4 iv = iv4[pass];
                u[pass][0] = xh[iv.x + cc];
                u[pass][1] = xh[iv.y + cc];
                u[pass][2] = xh[iv.z + cc];
                u[pass][3] = xh[iv.w + cc];
            }
        }

        // ---- MMA(c) ----
        {
            const uint32_t* Asx = As + (c & 1) * 128 * SA;
            const uint32_t* Bsx = Bs + (c & 1) * 128 * SA;
#pragma unroll
            for (int ks = 0; ks < 4; ks++) {
                int c0 = ks * 8 + t;
                uint32_t afrag[2][4];
#pragma unroll
                for (int mt = 0; mt < 2; mt++) {
                    int row = wpx0 + mt * 16 + g;
                    afrag[mt][0] = Asx[row * SA + c0];
                    afrag[mt][1] = Asx[(row + 8) * SA + c0];
                    afrag[mt][2] = Asx[row * SA + c0 + 4];
                    afrag[mt][3] = Asx[(row + 8) * SA + c0 + 4];
                }
                uint32_t bfrag[8][2];
#pragma unroll
                for (int nt = 0; nt < 8; nt++) {
                    int oc = woc0 + nt * 8 + g;
                    bfrag[nt][0] = Bsx[oc * SA + c0];
                    bfrag[nt][1] = Bsx[oc * SA + c0 + 4];
                }
#pragma unroll
                for (int mt = 0; mt < 2; mt++)
#pragma unroll
                    for (int nt = 0; nt < 8; nt++)
                        mma_f16(acc[mt][nt], afrag[mt], bfrag[nt]);
            }
        }

        // ---- interp + STS for chunk c+1 ----
        if (c < 17) {
            int ntap = (c + 1) >> 1;
            uint32_t* Asn = As + ((c + 1) & 1) * 128 * SA;
#pragma unroll
            for (int pass = 0; pass < 4; pass++) {
                float4 wv = g_bw[pbase + ntap * PLANE + pixp[pass]];
                uint32_t pk[4];
#pragma unroll
                for (int j = 0; j < 4; j++) {
                    float2 f00 = __half22float2(*(__half2*)&((uint32_t*)&u[pass][0])[j]);
                    float2 f01 = __half22float2(*(__half2*)&((uint32_t*)&u[pass][1])[j]);
                    float2 f10 = __half22float2(*(__half2*)&((uint32_t*)&u[pass][2])[j]);
                    float2 f11 = __half22float2(*(__half2*)&((uint32_t*)&u[pass][3])[j]);
                    float rl = wv.x * f00.x + wv.y * f01.x + wv.z * f10.x + wv.w * f11.x;
                    float rh = wv.x * f00.y + wv.y * f01.y + wv.z * f10.y + wv.w * f11.y;
                    pk[j] = pack_h2(rl, rh);
                }
                *(uint4*)&Asn[(pass * 32 + gp) * SA + gc * 4] = *(uint4*)pk;
            }
        }
    }

    // ---- epilogue: acc -> out (NCHW) + bias ----
    int e_ho = ho0 + (wid & 3);
    float* ob = out + ((size_t)b * COUT) * PLANE + (size_t)e_ho * WW + wo0;
#pragma unroll
    for (int nt = 0; nt < 8; nt++) {
        int oc0 = woc0 + nt * 8 + 2 * t;
        float b0 = __ldg(&bias[oc0]);
        float b1 = __ldg(&bias[oc0 + 1]);
#pragma unroll
        for (int mt = 0; mt < 2; mt++) {
            int wo_a = mt * 16 + g;
            float* r0 = ob + (size_t)oc0 * PLANE + wo_a;
            float* r1 = ob + (size_t)(oc0 + 1) * PLANE + wo_a;
            r0[0] = acc[mt][nt][0] + b0;
            r1[0] = acc[mt][nt][1] + b1;
            r0[8] = acc[mt][nt][2] + b0;
            r1[8] = acc[mt][nt][3] + b1;
        }
    }
}

// ============================================================
// launch
// ============================================================
extern "C" void kernel_launch(void* const* d_in, const int* in_sizes, int n_in,
                              void* d_out, int out_size) {
    (void)in_sizes; (void)n_in; (void)out_size;
    const float* x      = (const float*)d_in[0];
    const float* weight = (const float*)d_in[1];
    const float* bias   = (const float*)d_in[2];
    const float* w_off  = (const float*)d_in[3];

    float* out = (float*)d_out;
    float* off = out + OUT_MAIN_ELEMS;   // second output: offsets [B,18,H,W]

    const int DSMEM_DEF = (4 * 128 * SA) * 4;              // 73728 B
    const int DSMEM_OFF = (3 * 256 * SA + 3 * 32 * SA) * 4; // 124416 B
    cudaFuncSetAttribute(deform_mma, cudaFuncAttributeMaxDynamicSharedMemorySize, DSMEM_DEF);
    cudaFuncSetAttribute(offset_mma, cudaFuncAttributeMaxDynamicSharedMemorySize, DSMEM_OFF);

    transpose_to_fp16<<<dim3(WW / 32, CIN / 32, BB * HH), dim3(32, 8)>>>(x);
    prep_weights<<<(18 * 128 * 32 + 255) / 256, 256>>>(weight, w_off);
    offset_mma<<<(BB * PLANE) / 256, 256, DSMEM_OFF>>>(off);
    prep_bilinear<<<(BB * K2 * PLANE + 255) / 256, 256>>>(off);
    deform_mma<<<dim3(WW / 32, HH / 4, BB), 256, DSMEM_DEF>>>(bias, out);
}